// round 15
// baseline (speedup 1.0000x reference)
#include <cuda_runtime.h>
#include <math.h>
#include <stdint.h>

// ---------------- problem constants ----------------
#define BATCH 128
#define HDIM  512
#define TZ    64
#define TU    128
#define DDIM  5
#define VOC   8000
#define GINR  1541
#define GINP  1552
#define NG    1536
#define PV    8064
#define SLD   16064

// ---------------- scratch offsets (floats) ----------------
#define OFF_PPZ    0                             // 8 x 128x512
#define OFF_PPU    (OFF_PPZ + 524288)            // 8 x 128x512
#define OFF_PREZ   (OFF_PPU + 524288)
#define OFF_PREU   (OFF_PREZ + 65536)
#define OFF_PARTZ  (OFF_PREU + 65536)            // 8192*4
#define OFF_PARTU  (OFF_PARTZ + 32768)           // 16384*4
#define OFF_PARTGH (OFF_PARTU + 65536)           // 8 x 128x1536
#define OFF_PARTGI (OFF_PARTGH + 1572864)        // 13 x 128x1536
#define OFF_PARTPJ (OFF_PARTGI + 2555904)        // 8 x 128x8000
#define OFF_P      (OFF_PARTPJ + 8192000)        // 128x1024 [z|u]
#define OFF_G      (OFF_P + 131072)              // 128x1024 [u|z]
#define OFF_MEMB   (OFF_G + 131072)              // 128x512
#define OFF_DEGP   (OFF_MEMB + 65536)            // 128x16
#define OFF_GI     (OFF_DEGP + 2048)
#define OFF_GH     (OFF_GI + 196608)
#define OFF_HNEW   (OFF_GH + 196608)
#define OFF_HNEWR  (OFF_HNEW + 65536)
#define OFF_S      (OFF_HNEWR + 65536)           // 128x16064
#define OFF_EZ     (OFF_S + 2056192)
#define OFF_MZ     (OFF_EZ + 8192)
#define OFF_WIHP   (OFF_MZ + 128)                // 1536x1552
#define OFF_CS     (OFF_WIHP + 2383872)          // 8192x512
#define SCRATCH_FLOATS (OFF_CS + 4194304)

__device__ float g_scratch[SCRATCH_FLOATS];

// ---------------- helpers ----------------
__device__ __forceinline__ float ftanh(float x) {
    float e = __expf(2.f * x);
    return 1.f - __fdividef(2.f, e + 1.f);
}

__device__ __forceinline__ uint32_t f2tf32(float f) {
    uint32_t r;
    asm("cvt.rna.tf32.f32 %0, %1;" : "=r"(r) : "f"(f));
    return r;
}

__device__ __forceinline__ void mma_tf32(float* c, const uint32_t* a,
                                         uint32_t b0, uint32_t b1) {
    asm volatile(
        "mma.sync.aligned.m16n8k8.row.col.f32.tf32.tf32.f32 "
        "{%0,%1,%2,%3}, {%4,%5,%6,%7}, {%8,%9}, {%0,%1,%2,%3};"
        : "+f"(c[0]), "+f"(c[1]), "+f"(c[2]), "+f"(c[3])
        : "r"(a[0]), "r"(a[1]), "r"(a[2]), "r"(a[3]), "r"(b0), "r"(b1));
}

// ---------------- TF32 NT GEMM, cp.async 5-stage pipeline ----------------
// Operands raw fp32 (mma truncates to tf32).
// C = A(MxK, lda) @ Bw(NxK, ldb, +bofs)^T
// EPI=0: plain; splitK via gridDim.z (slice z at C + z*M*ldc, no bias);
//        if gridDim.z==1 and bias, bias added inline.
// EPI=1: fused score partials: sum_col ftanh(acc + pre[b*N+col]) * wvec[col],
//        b = row % BATCH (pre holds reduced hidden-projection incl. bias).
// EPI=2: write ftanh(acc + bias) elementwise (nz must be 1).
#define BM 128
#define BN 128
#define BK 16
#define PAD 20
#define STAGES 5
#define TSTRIDE (BM * PAD)
#define GSMEM (STAGES * 2 * TSTRIDE * 4)  // 102400 bytes

template<int EPI>
__global__ void __launch_bounds__(256, 2)
gemm_tf32(const float* __restrict__ A, int lda,
          const float* __restrict__ Bw, int ldb, int bofs,
          const float* __restrict__ bias,
          const float* __restrict__ pre,
          const float* __restrict__ wvec,
          float* __restrict__ C, int ldc,
          int M, int N, int K)
{
    extern __shared__ uint32_t dsm[];
    uint32_t* AsBase = dsm;
    uint32_t* BsBase = dsm + STAGES * TSTRIDE;
    __shared__ float red[BM][2];

    const int tid = threadIdx.x;
    const int lane = tid & 31, wid = tid >> 5;
    const int warpRow = wid & 3, warpCol = wid >> 2;
    const int row0 = blockIdx.y * BM, col0 = blockIdx.x * BN;

    const int nkTot = K / BK;
    const int nz = gridDim.z;
    const int kPer = (nkTot + nz - 1) / nz;
    const int kt0 = blockIdx.z * kPer;
    int kt1 = kt0 + kPer; if (kt1 > nkTot) kt1 = nkTot;
    const int nk = kt1 - kt0;

    const int lr = tid >> 2;
    const int lkq = (tid & 3) << 2;

    auto issue = [&](int kt, int st) {
        const int kbase = kt * BK + lkq;
        uint32_t* As = AsBase + st * TSTRIDE;
        uint32_t* Bs = BsBase + st * TSTRIDE;
        #pragma unroll
        for (int h = 0; h < 2; h++) {
            int r = lr + h * 64;
            const float* srcA = A + (size_t)(row0 + r) * lda + kbase;
            uint32_t dA = (uint32_t)__cvta_generic_to_shared(As + r * PAD + lkq);
            asm volatile("cp.async.cg.shared.global [%0], [%1], 16;"
                         :: "r"(dA), "l"(srcA));
            int cn = col0 + r;
            int ok = (cn < N) ? 16 : 0;
            const float* srcB = Bw + (size_t)(cn < N ? cn : 0) * ldb + bofs + kbase;
            uint32_t dB = (uint32_t)__cvta_generic_to_shared(Bs + r * PAD + lkq);
            asm volatile("cp.async.cg.shared.global [%0], [%1], 16, %2;"
                         :: "r"(dB), "l"(srcB), "r"(ok));
        }
    };

    float acc[2][8][4];
    #pragma unroll
    for (int i = 0; i < 2; i++)
        #pragma unroll
        for (int j = 0; j < 8; j++)
            #pragma unroll
            for (int l = 0; l < 4; l++) acc[i][j][l] = 0.f;

    // prologue: commit STAGES-1 groups (possibly empty)
    #pragma unroll
    for (int s = 0; s < STAGES - 1; s++) {
        if (s < nk) issue(kt0 + s, s);
        asm volatile("cp.async.commit_group;" ::: "memory");
    }

    int stC = 0;
    for (int it = 0; it < nk; it++) {
        asm volatile("cp.async.wait_group 3;" ::: "memory");
        __syncthreads();
        const uint32_t* As = AsBase + stC * TSTRIDE;
        const uint32_t* Bs = BsBase + stC * TSTRIDE;

        #pragma unroll
        for (int ks = 0; ks < 2; ks++) {
            const int k = ks * 8 + (lane & 3);
            uint32_t a[2][4];
            #pragma unroll
            for (int mi = 0; mi < 2; mi++) {
                int r = warpRow * 32 + mi * 16 + (lane >> 2);
                a[mi][0] = As[r * PAD + k];
                a[mi][1] = As[(r + 8) * PAD + k];
                a[mi][2] = As[r * PAD + k + 4];
                a[mi][3] = As[(r + 8) * PAD + k + 4];
            }
            #pragma unroll
            for (int ni = 0; ni < 8; ni++) {
                int cb = warpCol * 64 + ni * 8 + (lane >> 2);
                uint32_t b0 = Bs[cb * PAD + k];
                uint32_t b1 = Bs[cb * PAD + k + 4];
                #pragma unroll
                for (int mi = 0; mi < 2; mi++)
                    mma_tf32(acc[mi][ni], a[mi], b0, b1);
            }
        }

        int nxt = it + STAGES - 1;
        if (nxt < nk) {
            int stF = stC + STAGES - 1;
            if (stF >= STAGES) stF -= STAGES;
            issue(kt0 + nxt, stF);
        }
        asm volatile("cp.async.commit_group;" ::: "memory");
        stC = (stC + 1 == STAGES) ? 0 : stC + 1;
    }

    if (EPI != 1) {
        float* Cb = C + (size_t)blockIdx.z * ((size_t)M * ldc);
        #pragma unroll
        for (int mi = 0; mi < 2; mi++) {
            int r = row0 + warpRow * 32 + mi * 16 + (lane >> 2);
            #pragma unroll
            for (int ni = 0; ni < 8; ni++) {
                int cb = col0 + warpCol * 64 + ni * 8 + 2 * (lane & 3);
                float bs0 = (bias && cb < N)     ? bias[cb]     : 0.f;
                float bs1 = (bias && cb + 1 < N) ? bias[cb + 1] : 0.f;
                float v00 = acc[mi][ni][0] + bs0;
                float v01 = acc[mi][ni][1] + bs1;
                float v10 = acc[mi][ni][2] + bs0;
                float v11 = acc[mi][ni][3] + bs1;
                if (EPI == 2) {
                    v00 = ftanh(v00); v01 = ftanh(v01);
                    v10 = ftanh(v10); v11 = ftanh(v11);
                }
                if (cb < N)     Cb[(size_t)r * ldc + cb]           = v00;
                if (cb + 1 < N) Cb[(size_t)r * ldc + cb + 1]       = v01;
                if (cb < N)     Cb[(size_t)(r + 8) * ldc + cb]     = v10;
                if (cb + 1 < N) Cb[(size_t)(r + 8) * ldc + cb + 1] = v11;
            }
        }
    } else {
        #pragma unroll
        for (int mi = 0; mi < 2; mi++) {
            int rl = warpRow * 32 + mi * 16 + (lane >> 2);
            int bL = rl, bH = rl + 8;          // b = row % 128 (BM==BATCH)
            float s0 = 0.f, s1 = 0.f;
            #pragma unroll
            for (int ni = 0; ni < 8; ni++) {
                int colL = warpCol * 64 + ni * 8 + 2 * (lane & 3);
                #pragma unroll
                for (int j = 0; j < 2; j++) {
                    int gc = col0 + colL + j;
                    float e0 = ftanh(acc[mi][ni][j]     + pre[bL * N + gc]);
                    float e1 = ftanh(acc[mi][ni][2 + j] + pre[bH * N + gc]);
                    s0 += e0 * wvec[gc];
                    s1 += e1 * wvec[gc];
                }
            }
            s0 += __shfl_xor_sync(0xffffffffu, s0, 1);
            s0 += __shfl_xor_sync(0xffffffffu, s0, 2);
            s1 += __shfl_xor_sync(0xffffffffu, s1, 1);
            s1 += __shfl_xor_sync(0xffffffffu, s1, 2);
            if ((lane & 3) == 0) {
                red[rl][warpCol]     = s0;
                red[rl + 8][warpCol] = s1;
            }
        }
        __syncthreads();
        if (tid < BM) {
            float s = red[tid][0] + red[tid][1];
            C[(size_t)(row0 + tid) * gridDim.x + blockIdx.x] = s;
        }
    }
}

// sum split-K slices + bias -> dst
__global__ void reduceK(const float* __restrict__ part, int slices, int M, int N,
                        const float* __restrict__ bias, float* __restrict__ dst, int ldd)
{
    int i = blockIdx.x * blockDim.x + threadIdx.x;
    if (i >= M * N) return;
    int m = i / N, n = i - m * N;
    float s = bias ? bias[n] : 0.f;
    for (int z = 0; z < slices; z++) s += part[(size_t)z * M * N + i];
    dst[(size_t)m * ldd + n] = s;
}

// pad + tf32-round Wih
__global__ void padWih(const float* __restrict__ W, float* __restrict__ Wp)
{
    int i = blockIdx.x * blockDim.x + threadIdx.x;
    if (i >= NG * GINP) return;
    int n = i / GINP, k = i - n * GINP;
    float v = (k < GINR) ? W[(size_t)n * GINR + k] : 0.f;
    ((uint32_t*)Wp)[i] = f2tf32(v);
}

// build m_embed (128x512) and degree-pad (128x16)
__global__ void build_embdeg(const int* __restrict__ mt, const float* __restrict__ emb,
                             const float* __restrict__ degree,
                             float* __restrict__ memb, float* __restrict__ degp)
{
    int b = blockIdx.x, t = threadIdx.x;          // 128 threads
    int m = mt[b];
    float4 v = ((const float4*)emb)[(size_t)m * 128 + t];
    uint4 u;
    u.x = f2tf32(v.x); u.y = f2tf32(v.y); u.z = f2tf32(v.z); u.w = f2tf32(v.w);
    ((uint4*)memb)[b * 128 + t] = u;
    if (t < 16) {
        float d = (t < DDIM) ? degree[b * DDIM + t] : 0.f;
        ((uint32_t*)degp)[b * 16 + t] = f2tf32(d);
    }
}

// per-b softmax over T scores (score = sum of 4 packed n-block partials)
// + context into two concat slots (tf32-rounded)
__global__ void softmax_ctx(const float* __restrict__ part,   // [M][4]
                            const float* __restrict__ enc,    // (T,B,H)
                            float* __restrict__ d1,           // stride 1024
                            float* __restrict__ d2,           // stride 1024
                            int T)
{
    int b = blockIdx.x, tid = threadIdx.x;        // 128 threads
    __shared__ float sw[128];
    __shared__ float red[128];

    float v = -1e30f;
    if (tid < T) {
        float4 p = ((const float4*)part)[tid * BATCH + b];
        v = p.x + p.y + p.z + p.w;
    }
    red[tid] = v;
    __syncthreads();
    for (int s = 64; s > 0; s >>= 1) { if (tid < s) red[tid] = fmaxf(red[tid], red[tid + s]); __syncthreads(); }
    float mx = red[0];
    __syncthreads();

    float e = 0.f;
    if (tid < T) e = __expf(v - mx);
    red[tid] = e;
    __syncthreads();
    for (int s = 64; s > 0; s >>= 1) { if (tid < s) red[tid] += red[tid + s]; __syncthreads(); }
    float inv = __fdividef(1.f, red[0]);
    __syncthreads();
    sw[tid] = e * inv;
    __syncthreads();

    const float4* enc4 = (const float4*)enc;
    int h4 = tid;
    float4 acc = make_float4(0.f, 0.f, 0.f, 0.f);
    for (int t = 0; t < T; t++) {
        float w = sw[t];
        float4 x = enc4[((size_t)t * BATCH + b) * (HDIM / 4) + h4];
        acc.x += w * x.x; acc.y += w * x.y; acc.z += w * x.z; acc.w += w * x.w;
    }
    uint4 u;
    u.x = f2tf32(acc.x); u.y = f2tf32(acc.y); u.z = f2tf32(acc.z); u.w = f2tf32(acc.w);
    ((uint4*)(d1 + (size_t)b * 1024))[h4] = u;
    ((uint4*)(d2 + (size_t)b * 1024))[h4] = u;
}

// fused z_score matvec + per-b max + exp
__global__ void zscore_exp(const float* __restrict__ cs,
                           const float* __restrict__ hnew,
                           float* __restrict__ ez, float* __restrict__ mz)
{
    int b = blockIdx.x, tid = threadIdx.x;        // 256 threads, 8 warps
    __shared__ float4 h4[128];
    __shared__ float sc[64];
    __shared__ float red[64];
    if (tid < 128) h4[tid] = ((const float4*)(hnew + (size_t)b * HDIM))[tid];
    __syncthreads();
    int w = tid >> 5, lane = tid & 31;
    for (int t = w; t < TZ; t += 8) {
        const float4* crow = (const float4*)(cs + (size_t)(t * BATCH + b) * HDIM);
        float acc = 0.f;
        #pragma unroll
        for (int q = 0; q < 4; q++) {
            float4 c = crow[lane + 32 * q];
            float4 hh = h4[lane + 32 * q];
            acc += c.x * hh.x + c.y * hh.y + c.z * hh.z + c.w * hh.w;
        }
        #pragma unroll
        for (int s = 16; s > 0; s >>= 1) acc += __shfl_xor_sync(0xffffffffu, acc, s);
        if (lane == 0) sc[t] = acc;
    }
    __syncthreads();
    if (tid < 64) red[tid] = sc[tid];
    __syncthreads();
    for (int s = 32; s > 0; s >>= 1) { if (tid < s) red[tid] = fmaxf(red[tid], red[tid + s]); __syncthreads(); }
    float mx = red[0];
    if (tid < 64) ez[b * TZ + tid] = __expf(sc[tid] - mx);
    if (tid == 0) mz[b] = mx;
}

// z_copy -> S cols [VOC, VOC+PV)
__global__ void zcopy_kernel(const float* __restrict__ sp,
                             const float* __restrict__ ez,
                             const float* __restrict__ mz,
                             float* __restrict__ S)
{
    int b = blockIdx.y;
    int v4 = blockIdx.x * blockDim.x + threadIdx.x;
    __shared__ float e[TZ];
    if (threadIdx.x < TZ) e[threadIdx.x] = ez[b * TZ + threadIdx.x];
    __syncthreads();
    if (v4 < PV / 4) {
        const float4* row = (const float4*)(sp + (size_t)b * TZ * PV) + v4;
        float4 acc = make_float4(0.f, 0.f, 0.f, 0.f);
        #pragma unroll 8
        for (int t = 0; t < TZ; t++) {
            float w = e[t];
            float4 x = row[(size_t)t * (PV / 4)];
            acc.x += w * x.x; acc.y += w * x.y; acc.z += w * x.z; acc.w += w * x.w;
        }
        float m = mz[b];
        float* dst = S + (size_t)b * SLD + VOC + 4 * v4;
        dst[0] = __logf(acc.x) + m;
        dst[1] = __logf(acc.y) + m;
        dst[2] = __logf(acc.z) + m;
        dst[3] = __logf(acc.w) + m;
    }
}

// GRU gates -> h_new (exact) + hnewR (tf32-rounded); write gru_out x2
__global__ void gru_gate(const float* __restrict__ gi, const float* __restrict__ gh,
                         const float* __restrict__ hprev,
                         float* __restrict__ hnew, float* __restrict__ hnewR,
                         float* __restrict__ out, int out_size)
{
    int idx = blockIdx.x * blockDim.x + threadIdx.x;
    if (idx >= BATCH * HDIM) return;
    int b = idx >> 9, j = idx & 511;
    const float* gib = gi + (size_t)b * NG;
    const float* ghb = gh + (size_t)b * NG;
    float r = __fdividef(1.f, 1.f + __expf(-(gib[j]       + ghb[j])));
    float z = __fdividef(1.f, 1.f + __expf(-(gib[512 + j] + ghb[512 + j])));
    float n = ftanh(gib[1024 + j] + r * ghb[1024 + j]);
    float h = (1.f - z) * n + z * hprev[idx];
    hnew[idx] = h;
    ((uint32_t*)hnewR)[idx] = f2tf32(h);
    const int base = BATCH * PV;
    if (out_size >= base + BATCH * HDIM)     out[base + idx] = h;
    if (out_size >= base + 2 * BATCH * HDIM) out[base + BATCH * HDIM + idx] = h;
}

__global__ void final_softmax(const float* __restrict__ S, float* __restrict__ out)
{
    int b = blockIdx.x, tid = threadIdx.x;
    __shared__ float red[256];
    const float4* row4 = (const float4*)(S + (size_t)b * SLD);
    const int n4 = SLD / 4;

    float mx = -1e30f;
    for (int i = tid; i < n4; i += 256) {
        float4 x = row4[i];
        mx = fmaxf(mx, fmaxf(fmaxf(x.x, x.y), fmaxf(x.z, x.w)));
    }
    red[tid] = mx;
    __syncthreads();
    for (int s = 128; s > 0; s >>= 1) { if (tid < s) red[tid] = fmaxf(red[tid], red[tid + s]); __syncthreads(); }
    mx = red[0];
    __syncthreads();

    float sm = 0.f;
    for (int i = tid; i < n4; i += 256) {
        float4 x = row4[i];
        sm += __expf(x.x - mx) + __expf(x.y - mx) + __expf(x.z - mx) + __expf(x.w - mx);
    }
    red[tid] = sm;
    __syncthreads();
    for (int s = 128; s > 0; s >>= 1) { if (tid < s) red[tid] += red[tid + s]; __syncthreads(); }
    float inv = __fdividef(1.f, red[0]);

    const float4* cp4 = (const float4*)(S + (size_t)b * SLD + VOC);
    float4* out4 = (float4*)(out + (size_t)b * PV);
    for (int i = tid; i < PV / 4; i += 256) {
        float4 c = cp4[i];
        float4 o;
        o.x = __expf(c.x - mx) * inv;
        o.y = __expf(c.y - mx) * inv;
        o.z = __expf(c.z - mx) * inv;
        o.w = __expf(c.w - mx) * inv;
        if (i < VOC / 4) {
            float4 g = row4[i];
            o.x += __expf(g.x - mx) * inv;
            o.y += __expf(g.y - mx) * inv;
            o.z += __expf(g.z - mx) * inv;
            o.w += __expf(g.w - mx) * inv;
        }
        out4[i] = o;
    }
}

// ---------------------------------------------------------------------------
static cudaStream_t g_s1, g_s2, g_s3;
static cudaEvent_t g_evRoot, g_evWP, g_evZ, g_evU, g_evGH, g_evG, g_evCS, g_evS;
static bool g_init = false;

extern "C" void kernel_launch(void* const* d_in, const int* in_sizes, int n_in,
                              void* d_out, int out_size)
{
    if (!g_init) {
        cudaStreamCreateWithFlags(&g_s1, cudaStreamNonBlocking);
        cudaStreamCreateWithFlags(&g_s2, cudaStreamNonBlocking);
        cudaStreamCreateWithFlags(&g_s3, cudaStreamNonBlocking);
        cudaEventCreateWithFlags(&g_evRoot, cudaEventDisableTiming);
        cudaEventCreateWithFlags(&g_evWP,   cudaEventDisableTiming);
        cudaEventCreateWithFlags(&g_evZ,    cudaEventDisableTiming);
        cudaEventCreateWithFlags(&g_evU,    cudaEventDisableTiming);
        cudaEventCreateWithFlags(&g_evGH,   cudaEventDisableTiming);
        cudaEventCreateWithFlags(&g_evG,    cudaEventDisableTiming);
        cudaEventCreateWithFlags(&g_evCS,   cudaEventDisableTiming);
        cudaEventCreateWithFlags(&g_evS,    cudaEventDisableTiming);
        cudaFuncSetAttribute(gemm_tf32<0>, cudaFuncAttributeMaxDynamicSharedMemorySize, GSMEM);
        cudaFuncSetAttribute(gemm_tf32<1>, cudaFuncAttributeMaxDynamicSharedMemorySize, GSMEM);
        cudaFuncSetAttribute(gemm_tf32<2>, cudaFuncAttributeMaxDynamicSharedMemorySize, GSMEM);
        g_init = true;
    }

    const float* z_enc  = (const float*)d_in[0];
    const float* u_enc  = (const float*)d_in[1];
    const int*   mt     = (const int*)d_in[2];
    const float* degree = (const float*)d_in[3];
    const float* hid    = (const float*)d_in[4];
    const float* sp     = (const float*)d_in[5];
    const float* emb    = (const float*)d_in[6];
    const float* azW    = (const float*)d_in[7];
    const float* azb    = (const float*)d_in[8];
    const float* azv    = (const float*)d_in[9];
    const float* auW    = (const float*)d_in[10];
    const float* aub    = (const float*)d_in[11];
    const float* auv    = (const float*)d_in[12];
    const float* Wih    = (const float*)d_in[13];
    const float* Whh    = (const float*)d_in[14];
    const float* bih    = (const float*)d_in[15];
    const float* bhh    = (const float*)d_in[16];
    const float* pW     = (const float*)d_in[17];
    const float* pb     = (const float*)d_in[18];
    const float* c2W    = (const float*)d_in[19];
    const float* c2b    = (const float*)d_in[20];
    float* out = (float*)d_out;

    float* base = nullptr;
    cudaGetSymbolAddress((void**)&base, g_scratch);
    float* ppz    = base + OFF_PPZ;
    float* ppu    = base + OFF_PPU;
    float* preZ   = base + OFF_PREZ;
    float* preU   = base + OFF_PREU;
    float* partZ  = base + OFF_PARTZ;
    float* partU  = base + OFF_PARTU;
    float* partGH = base + OFF_PARTGH;
    float* partGI = base + OFF_PARTGI;
    float* partPJ = base + OFF_PARTPJ;
    float* P      = base + OFF_P;
    float* G      = base + OFF_G;
    float* memb   = base + OFF_MEMB;
    float* degp   = base + OFF_DEGP;
    float* gi     = base + OFF_GI;
    float* gh     = base + OFF_GH;
    float* hnew   = base + OFF_HNEW;
    float* hnewR  = base + OFF_HNEWR;
    float* S      = base + OFF_S;
    float* ez     = base + OFF_EZ;
    float* mz     = base + OFF_MZ;
    float* Wihp   = base + OFF_WIHP;
    float* cs     = base + OFF_CS;

    // ---- fork ----
    cudaEventRecord(g_evRoot, 0);
    cudaStreamWaitEvent(g_s1, g_evRoot, 0);
    cudaStreamWaitEvent(g_s2, g_evRoot, 0);
    cudaStreamWaitEvent(g_s3, g_evRoot, 0);

    // ---- s2: cs = tanh(z_enc @ c2W^T + c2b) at t=0 ----
    gemm_tf32<2><<<dim3(4, 64, 1), 256, GSMEM, g_s2>>>(z_enc, HDIM, c2W, HDIM, 0,
        c2b, nullptr, nullptr, cs, HDIM, TZ*BATCH, HDIM, HDIM);
    cudaEventRecord(g_evCS, g_s2);

    // ---- s3: Wih pad, embed/deg, gi0 (slices 0-3), gi2 (slice 4), gh (8 slices) ----
    padWih<<<(NG * GINP + 255) / 256, 256, 0, g_s3>>>(Wih, Wihp);
    build_embdeg<<<BATCH, 128, 0, g_s3>>>(mt, emb, degree, memb, degp);
    gemm_tf32<0><<<dim3(12, 1, 4), 256, GSMEM, g_s3>>>(memb, HDIM, Wihp, GINP, 0,
        nullptr, nullptr, nullptr, partGI, NG, BATCH, NG, HDIM);
    gemm_tf32<0><<<dim3(12, 1, 1), 256, GSMEM, g_s3>>>(degp, 16, Wihp, GINP, 1536,
        nullptr, nullptr, nullptr, partGI + 4 * (size_t)BATCH * NG, NG, BATCH, NG, 16);
    cudaEventRecord(g_evWP, g_s3);
    gemm_tf32<0><<<dim3(12, 1, 8), 256, GSMEM, g_s3>>>(hid, HDIM, Whh, HDIM, 0,
        nullptr, nullptr, nullptr, partGH, NG, BATCH, NG, HDIM);
    reduceK<<<(BATCH * NG + 255) / 256, 256, 0, g_s3>>>(partGH, 8, BATCH, NG, bhh, gh, NG);
    cudaEventRecord(g_evGH, g_s3);

    // ---- default: Z chain ----
    gemm_tf32<0><<<dim3(4, 1, 8), 256, GSMEM>>>(hid, HDIM, azW, 2*HDIM, 0,
        nullptr, nullptr, nullptr, ppz, HDIM, BATCH, HDIM, HDIM);
    reduceK<<<(BATCH * HDIM + 255) / 256, 256>>>(ppz, 8, BATCH, HDIM, azb, preZ, HDIM);
    gemm_tf32<1><<<dim3(4, 64, 1), 256, GSMEM>>>(z_enc, HDIM, azW, 2*HDIM, HDIM,
        nullptr, preZ, azv, partZ, 0, TZ*BATCH, HDIM, HDIM);
    softmax_ctx<<<BATCH, 128>>>(partZ, z_enc, P, G + 512, TZ);
    cudaEventRecord(g_evZ, 0);

    // ---- s1: U chain ----
    gemm_tf32<0><<<dim3(4, 1, 8), 256, GSMEM, g_s1>>>(hid, HDIM, auW, 2*HDIM, 0,
        nullptr, nullptr, nullptr, ppu, HDIM, BATCH, HDIM, HDIM);
    reduceK<<<(BATCH * HDIM + 255) / 256, 256, 0, g_s1>>>(ppu, 8, BATCH, HDIM, aub, preU, HDIM);
    gemm_tf32<1><<<dim3(4, 128, 1), 256, GSMEM, g_s1>>>(u_enc, HDIM, auW, 2*HDIM, HDIM,
        nullptr, preU, auv, partU, 0, TU*BATCH, HDIM, HDIM);
    softmax_ctx<<<BATCH, 128, 0, g_s1>>>(partU, u_enc, P + 512, G, TU);
    cudaEventRecord(g_evU, g_s1);

    // ---- default: gi1 (slices 5-12, splitK=8) -> reduce(13) -> gru ----
    cudaStreamWaitEvent(0, g_evU, 0);
    cudaStreamWaitEvent(0, g_evWP, 0);
    gemm_tf32<0><<<dim3(12, 1, 8), 256, GSMEM>>>(G, 1024, Wihp, GINP, 512,
        nullptr, nullptr, nullptr, partGI + 5 * (size_t)BATCH * NG, NG, BATCH, NG, 1024);
    reduceK<<<(BATCH * NG + 255) / 256, 256>>>(partGI, 13, BATCH, NG, bih, gi, NG);
    cudaStreamWaitEvent(0, g_evGH, 0);
    gru_gate<<<(BATCH * HDIM) / 256, 256>>>(gi, gh, hid, hnew, hnewR, out, out_size);
    cudaEventRecord(g_evG, 0);

    // ---- s1: proj1 (ctx, slices 0-3) then proj2 (hnew, slices 4-7) ----
    cudaStreamWaitEvent(g_s1, g_evZ, 0);
    gemm_tf32<0><<<dim3(63, 1, 4), 256, GSMEM, g_s1>>>(P, 1024, pW, NG, 0,
        nullptr, nullptr, nullptr, partPJ, VOC, BATCH, VOC, 1024);
    cudaStreamWaitEvent(g_s1, g_evG, 0);
    gemm_tf32<0><<<dim3(63, 1, 4), 256, GSMEM, g_s1>>>(hnewR, HDIM, pW, NG, 1024,
        nullptr, nullptr, nullptr, partPJ + 4 * (size_t)BATCH * VOC, VOC, BATCH, VOC, HDIM);
    reduceK<<<(BATCH * VOC + 255) / 256, 256, 0, g_s1>>>(partPJ, 8, BATCH, VOC, pb, S, SLD);
    cudaEventRecord(g_evS, g_s1);

    // ---- default: fused zscore+exp -> zcopy ----
    cudaStreamWaitEvent(0, g_evCS, 0);
    zscore_exp<<<BATCH, 256>>>(cs, hnew, ez, mz);
    zcopy_kernel<<<dim3((PV / 4 + 255) / 256, BATCH), 256>>>(sp, ez, mz, S);

    // ---- join; final ----
    cudaStreamWaitEvent(0, g_evS, 0);
    final_softmax<<<BATCH, 256>>>(S, out);
}

// round 16
// speedup vs baseline: 1.2058x; 1.2058x over previous
#include <cuda_runtime.h>
#include <math.h>
#include <stdint.h>

// ---------------- problem constants ----------------
#define BATCH 128
#define HDIM  512
#define TZ    64
#define TU    128
#define DDIM  5
#define VOC   8000
#define GINR  1541
#define GINP  1552
#define NG    1536
#define PV    8064
#define SLD   16064

// ---------------- scratch offsets (floats) ----------------
#define OFF_PPZ    0                             // 8 x 128x512
#define OFF_PPU    (OFF_PPZ + 524288)            // 8 x 128x512
#define OFF_PREZ   (OFF_PPU + 524288)
#define OFF_PREU   (OFF_PREZ + 65536)
#define OFF_PARTZ  (OFF_PREU + 65536)            // 8192*4
#define OFF_PARTU  (OFF_PARTZ + 32768)           // 16384*4
#define OFF_PARTGH (OFF_PARTU + 65536)           // 8 x 128x1536
#define OFF_PARTGI (OFF_PARTGH + 1572864)        // 13 x 128x1536
#define OFF_PARTPJ (OFF_PARTGI + 2555904)        // 4 x 128x8000
#define OFF_P      (OFF_PARTPJ + 4096000)        // 128x1024 [z|u]
#define OFF_G      (OFF_P + 131072)              // 128x1024 [u|z]
#define OFF_MEMB   (OFF_G + 131072)              // 128x512
#define OFF_DEGP   (OFF_MEMB + 65536)            // 128x16
#define OFF_GI     (OFF_DEGP + 2048)
#define OFF_GH     (OFF_GI + 196608)
#define OFF_HNEW   (OFF_GH + 196608)
#define OFF_HNEWR  (OFF_HNEW + 65536)
#define OFF_S      (OFF_HNEWR + 65536)           // 128x16064
#define OFF_EZ     (OFF_S + 2056192)
#define OFF_MZ     (OFF_EZ + 8192)
#define OFF_WIHP   (OFF_MZ + 128)                // 1536x1552
#define OFF_CS     (OFF_WIHP + 2383872)          // 8192x512
#define SCRATCH_FLOATS (OFF_CS + 4194304)

__device__ float g_scratch[SCRATCH_FLOATS];

// ---------------- helpers ----------------
__device__ __forceinline__ float ftanh(float x) {
    float e = __expf(2.f * x);
    return 1.f - __fdividef(2.f, e + 1.f);
}

__device__ __forceinline__ uint32_t f2tf32(float f) {
    uint32_t r;
    asm("cvt.rna.tf32.f32 %0, %1;" : "=r"(r) : "f"(f));
    return r;
}

__device__ __forceinline__ void mma_tf32(float* c, const uint32_t* a,
                                         uint32_t b0, uint32_t b1) {
    asm volatile(
        "mma.sync.aligned.m16n8k8.row.col.f32.tf32.tf32.f32 "
        "{%0,%1,%2,%3}, {%4,%5,%6,%7}, {%8,%9}, {%0,%1,%2,%3};"
        : "+f"(c[0]), "+f"(c[1]), "+f"(c[2]), "+f"(c[3])
        : "r"(a[0]), "r"(a[1]), "r"(a[2]), "r"(a[3]), "r"(b0), "r"(b1));
}

// ---------------- TF32 NT GEMM, cp.async 4-stage pipeline ----------------
// Operands raw fp32 (mma truncates to tf32).
// C = A(MxK, lda) @ Bw(NxK, ldb, +bofs)^T
// EPI=0: plain; splitK via gridDim.z (slice z at C + z*M*ldc, no bias);
//        if gridDim.z==1 and bias, bias added inline.
// EPI=1: fused score partials: sum_col ftanh(acc + pre[b*N+col]) * wvec[col],
//        b = row % BATCH (pre holds reduced hidden-projection incl. bias).
// EPI=2: write ftanh(acc + bias) elementwise (nz must be 1).
#define BM 128
#define BN 128
#define BK 16
#define PAD 20
#define STAGES 4
#define TSTRIDE (BM * PAD)
#define GSMEM (STAGES * 2 * TSTRIDE * 4)  // 81920 bytes

template<int EPI>
__global__ void __launch_bounds__(256, 2)
gemm_tf32(const float* __restrict__ A, int lda,
          const float* __restrict__ Bw, int ldb, int bofs,
          const float* __restrict__ bias,
          const float* __restrict__ pre,
          const float* __restrict__ wvec,
          float* __restrict__ C, int ldc,
          int M, int N, int K)
{
    extern __shared__ uint32_t dsm[];
    uint32_t* AsBase = dsm;
    uint32_t* BsBase = dsm + STAGES * TSTRIDE;
    __shared__ float red[BM][2];

    const int tid = threadIdx.x;
    const int lane = tid & 31, wid = tid >> 5;
    const int warpRow = wid & 3, warpCol = wid >> 2;
    const int row0 = blockIdx.y * BM, col0 = blockIdx.x * BN;

    const int nkTot = K / BK;
    const int nz = gridDim.z;
    const int kPer = (nkTot + nz - 1) / nz;
    const int kt0 = blockIdx.z * kPer;
    int kt1 = kt0 + kPer; if (kt1 > nkTot) kt1 = nkTot;
    const int nk = kt1 - kt0;

    const int lr = tid >> 2;
    const int lkq = (tid & 3) << 2;

    auto issue = [&](int kt, int st) {
        const int kbase = kt * BK + lkq;
        uint32_t* As = AsBase + st * TSTRIDE;
        uint32_t* Bs = BsBase + st * TSTRIDE;
        #pragma unroll
        for (int h = 0; h < 2; h++) {
            int r = lr + h * 64;
            const float* srcA = A + (size_t)(row0 + r) * lda + kbase;
            uint32_t dA = (uint32_t)__cvta_generic_to_shared(As + r * PAD + lkq);
            asm volatile("cp.async.cg.shared.global [%0], [%1], 16;"
                         :: "r"(dA), "l"(srcA));
            int cn = col0 + r;
            int ok = (cn < N) ? 16 : 0;
            const float* srcB = Bw + (size_t)(cn < N ? cn : 0) * ldb + bofs + kbase;
            uint32_t dB = (uint32_t)__cvta_generic_to_shared(Bs + r * PAD + lkq);
            asm volatile("cp.async.cg.shared.global [%0], [%1], 16, %2;"
                         :: "r"(dB), "l"(srcB), "r"(ok));
        }
    };

    float acc[2][8][4];
    #pragma unroll
    for (int i = 0; i < 2; i++)
        #pragma unroll
        for (int j = 0; j < 8; j++)
            #pragma unroll
            for (int l = 0; l < 4; l++) acc[i][j][l] = 0.f;

    #pragma unroll
    for (int s = 0; s < STAGES - 1; s++) {
        if (s < nk) issue(kt0 + s, s);
        asm volatile("cp.async.commit_group;" ::: "memory");
    }

    int stC = 0;
    for (int it = 0; it < nk; it++) {
        asm volatile("cp.async.wait_group 2;" ::: "memory");
        __syncthreads();
        const uint32_t* As = AsBase + stC * TSTRIDE;
        const uint32_t* Bs = BsBase + stC * TSTRIDE;

        #pragma unroll
        for (int ks = 0; ks < 2; ks++) {
            const int k = ks * 8 + (lane & 3);
            uint32_t a[2][4];
            #pragma unroll
            for (int mi = 0; mi < 2; mi++) {
                int r = warpRow * 32 + mi * 16 + (lane >> 2);
                a[mi][0] = As[r * PAD + k];
                a[mi][1] = As[(r + 8) * PAD + k];
                a[mi][2] = As[r * PAD + k + 4];
                a[mi][3] = As[(r + 8) * PAD + k + 4];
            }
            #pragma unroll
            for (int ni = 0; ni < 8; ni++) {
                int cb = warpCol * 64 + ni * 8 + (lane >> 2);
                uint32_t b0 = Bs[cb * PAD + k];
                uint32_t b1 = Bs[cb * PAD + k + 4];
                #pragma unroll
                for (int mi = 0; mi < 2; mi++)
                    mma_tf32(acc[mi][ni], a[mi], b0, b1);
            }
        }

        int nxt = it + STAGES - 1;
        if (nxt < nk) issue(kt0 + nxt, nxt & (STAGES - 1));
        asm volatile("cp.async.commit_group;" ::: "memory");
        stC = (stC + 1) & (STAGES - 1);
    }

    if (EPI != 1) {
        float* Cb = C + (size_t)blockIdx.z * ((size_t)M * ldc);
        #pragma unroll
        for (int mi = 0; mi < 2; mi++) {
            int r = row0 + warpRow * 32 + mi * 16 + (lane >> 2);
            #pragma unroll
            for (int ni = 0; ni < 8; ni++) {
                int cb = col0 + warpCol * 64 + ni * 8 + 2 * (lane & 3);
                float bs0 = (bias && cb < N)     ? bias[cb]     : 0.f;
                float bs1 = (bias && cb + 1 < N) ? bias[cb + 1] : 0.f;
                float v00 = acc[mi][ni][0] + bs0;
                float v01 = acc[mi][ni][1] + bs1;
                float v10 = acc[mi][ni][2] + bs0;
                float v11 = acc[mi][ni][3] + bs1;
                if (EPI == 2) {
                    v00 = ftanh(v00); v01 = ftanh(v01);
                    v10 = ftanh(v10); v11 = ftanh(v11);
                }
                if (cb < N)     Cb[(size_t)r * ldc + cb]           = v00;
                if (cb + 1 < N) Cb[(size_t)r * ldc + cb + 1]       = v01;
                if (cb < N)     Cb[(size_t)(r + 8) * ldc + cb]     = v10;
                if (cb + 1 < N) Cb[(size_t)(r + 8) * ldc + cb + 1] = v11;
            }
        }
    } else {
        #pragma unroll
        for (int mi = 0; mi < 2; mi++) {
            int rl = warpRow * 32 + mi * 16 + (lane >> 2);
            int bL = rl, bH = rl + 8;          // b = row % 128 (BM==BATCH)
            float s0 = 0.f, s1 = 0.f;
            #pragma unroll
            for (int ni = 0; ni < 8; ni++) {
                int colL = warpCol * 64 + ni * 8 + 2 * (lane & 3);
                #pragma unroll
                for (int j = 0; j < 2; j++) {
                    int gc = col0 + colL + j;
                    float e0 = ftanh(acc[mi][ni][j]     + pre[bL * N + gc]);
                    float e1 = ftanh(acc[mi][ni][2 + j] + pre[bH * N + gc]);
                    s0 += e0 * wvec[gc];
                    s1 += e1 * wvec[gc];
                }
            }
            s0 += __shfl_xor_sync(0xffffffffu, s0, 1);
            s0 += __shfl_xor_sync(0xffffffffu, s0, 2);
            s1 += __shfl_xor_sync(0xffffffffu, s1, 1);
            s1 += __shfl_xor_sync(0xffffffffu, s1, 2);
            if ((lane & 3) == 0) {
                red[rl][warpCol]     = s0;
                red[rl + 8][warpCol] = s1;
            }
        }
        __syncthreads();
        if (tid < BM) {
            float s = red[tid][0] + red[tid][1];
            C[(size_t)(row0 + tid) * gridDim.x + blockIdx.x] = s;
        }
    }
}

// sum split-K slices + bias -> dst
__global__ void reduceK(const float* __restrict__ part, int slices, int M, int N,
                        const float* __restrict__ bias, float* __restrict__ dst, int ldd)
{
    int i = blockIdx.x * blockDim.x + threadIdx.x;
    if (i >= M * N) return;
    int m = i / N, n = i - m * N;
    float s = bias ? bias[n] : 0.f;
    for (int z = 0; z < slices; z++) s += part[(size_t)z * M * N + i];
    dst[(size_t)m * ldd + n] = s;
}

// pad + tf32-round Wih
__global__ void padWih(const float* __restrict__ W, float* __restrict__ Wp)
{
    int i = blockIdx.x * blockDim.x + threadIdx.x;
    if (i >= NG * GINP) return;
    int n = i / GINP, k = i - n * GINP;
    float v = (k < GINR) ? W[(size_t)n * GINR + k] : 0.f;
    ((uint32_t*)Wp)[i] = f2tf32(v);
}

// build m_embed (128x512) and degree-pad (128x16)
__global__ void build_embdeg(const int* __restrict__ mt, const float* __restrict__ emb,
                             const float* __restrict__ degree,
                             float* __restrict__ memb, float* __restrict__ degp)
{
    int b = blockIdx.x, t = threadIdx.x;          // 128 threads
    int m = mt[b];
    float4 v = ((const float4*)emb)[(size_t)m * 128 + t];
    uint4 u;
    u.x = f2tf32(v.x); u.y = f2tf32(v.y); u.z = f2tf32(v.z); u.w = f2tf32(v.w);
    ((uint4*)memb)[b * 128 + t] = u;
    if (t < 16) {
        float d = (t < DDIM) ? degree[b * DDIM + t] : 0.f;
        ((uint32_t*)degp)[b * 16 + t] = f2tf32(d);
    }
}

// per-b softmax over T scores (score = sum of 4 packed n-block partials)
// + context into two concat slots (tf32-rounded)
__global__ void softmax_ctx(const float* __restrict__ part,   // [M][4]
                            const float* __restrict__ enc,    // (T,B,H)
                            float* __restrict__ d1,           // stride 1024
                            float* __restrict__ d2,           // stride 1024
                            int T)
{
    int b = blockIdx.x, tid = threadIdx.x;        // 128 threads
    __shared__ float sw[128];
    __shared__ float red[128];

    float v = -1e30f;
    if (tid < T) {
        float4 p = ((const float4*)part)[tid * BATCH + b];
        v = p.x + p.y + p.z + p.w;
    }
    red[tid] = v;
    __syncthreads();
    for (int s = 64; s > 0; s >>= 1) { if (tid < s) red[tid] = fmaxf(red[tid], red[tid + s]); __syncthreads(); }
    float mx = red[0];
    __syncthreads();

    float e = 0.f;
    if (tid < T) e = __expf(v - mx);
    red[tid] = e;
    __syncthreads();
    for (int s = 64; s > 0; s >>= 1) { if (tid < s) red[tid] += red[tid + s]; __syncthreads(); }
    float inv = __fdividef(1.f, red[0]);
    __syncthreads();
    sw[tid] = e * inv;
    __syncthreads();

    const float4* enc4 = (const float4*)enc;
    int h4 = tid;
    float4 acc = make_float4(0.f, 0.f, 0.f, 0.f);
    for (int t = 0; t < T; t++) {
        float w = sw[t];
        float4 x = enc4[((size_t)t * BATCH + b) * (HDIM / 4) + h4];
        acc.x += w * x.x; acc.y += w * x.y; acc.z += w * x.z; acc.w += w * x.w;
    }
    uint4 u;
    u.x = f2tf32(acc.x); u.y = f2tf32(acc.y); u.z = f2tf32(acc.z); u.w = f2tf32(acc.w);
    ((uint4*)(d1 + (size_t)b * 1024))[h4] = u;
    ((uint4*)(d2 + (size_t)b * 1024))[h4] = u;
}

// fused z_score matvec + per-b max + exp
__global__ void zscore_exp(const float* __restrict__ cs,
                           const float* __restrict__ hnew,
                           float* __restrict__ ez, float* __restrict__ mz)
{
    int b = blockIdx.x, tid = threadIdx.x;        // 256 threads, 8 warps
    __shared__ float4 h4[128];
    __shared__ float sc[64];
    __shared__ float red[64];
    if (tid < 128) h4[tid] = ((const float4*)(hnew + (size_t)b * HDIM))[tid];
    __syncthreads();
    int w = tid >> 5, lane = tid & 31;
    for (int t = w; t < TZ; t += 8) {
        const float4* crow = (const float4*)(cs + (size_t)(t * BATCH + b) * HDIM);
        float acc = 0.f;
        #pragma unroll
        for (int q = 0; q < 4; q++) {
            float4 c = crow[lane + 32 * q];
            float4 hh = h4[lane + 32 * q];
            acc += c.x * hh.x + c.y * hh.y + c.z * hh.z + c.w * hh.w;
        }
        #pragma unroll
        for (int s = 16; s > 0; s >>= 1) acc += __shfl_xor_sync(0xffffffffu, acc, s);
        if (lane == 0) sc[t] = acc;
    }
    __syncthreads();
    if (tid < 64) red[tid] = sc[tid];
    __syncthreads();
    for (int s = 32; s > 0; s >>= 1) { if (tid < s) red[tid] = fmaxf(red[tid], red[tid + s]); __syncthreads(); }
    float mx = red[0];
    if (tid < 64) ez[b * TZ + tid] = __expf(sc[tid] - mx);
    if (tid == 0) mz[b] = mx;
}

// z_copy -> S cols [VOC, VOC+PV)
__global__ void zcopy_kernel(const float* __restrict__ sp,
                             const float* __restrict__ ez,
                             const float* __restrict__ mz,
                             float* __restrict__ S)
{
    int b = blockIdx.y;
    int v4 = blockIdx.x * blockDim.x + threadIdx.x;
    __shared__ float e[TZ];
    if (threadIdx.x < TZ) e[threadIdx.x] = ez[b * TZ + threadIdx.x];
    __syncthreads();
    if (v4 < PV / 4) {
        const float4* row = (const float4*)(sp + (size_t)b * TZ * PV) + v4;
        float4 acc = make_float4(0.f, 0.f, 0.f, 0.f);
        #pragma unroll 8
        for (int t = 0; t < TZ; t++) {
            float w = e[t];
            float4 x = row[(size_t)t * (PV / 4)];
            acc.x += w * x.x; acc.y += w * x.y; acc.z += w * x.z; acc.w += w * x.w;
        }
        float m = mz[b];
        float* dst = S + (size_t)b * SLD + VOC + 4 * v4;
        dst[0] = __logf(acc.x) + m;
        dst[1] = __logf(acc.y) + m;
        dst[2] = __logf(acc.z) + m;
        dst[3] = __logf(acc.w) + m;
    }
}

// GRU gates -> h_new (exact) + hnewR (tf32-rounded); write gru_out x2
__global__ void gru_gate(const float* __restrict__ gi, const float* __restrict__ gh,
                         const float* __restrict__ hprev,
                         float* __restrict__ hnew, float* __restrict__ hnewR,
                         float* __restrict__ out, int out_size)
{
    int idx = blockIdx.x * blockDim.x + threadIdx.x;
    if (idx >= BATCH * HDIM) return;
    int b = idx >> 9, j = idx & 511;
    const float* gib = gi + (size_t)b * NG;
    const float* ghb = gh + (size_t)b * NG;
    float r = __fdividef(1.f, 1.f + __expf(-(gib[j]       + ghb[j])));
    float z = __fdividef(1.f, 1.f + __expf(-(gib[512 + j] + ghb[512 + j])));
    float n = ftanh(gib[1024 + j] + r * ghb[1024 + j]);
    float h = (1.f - z) * n + z * hprev[idx];
    hnew[idx] = h;
    ((uint32_t*)hnewR)[idx] = f2tf32(h);
    const int base = BATCH * PV;
    if (out_size >= base + BATCH * HDIM)     out[base + idx] = h;
    if (out_size >= base + 2 * BATCH * HDIM) out[base + BATCH * HDIM + idx] = h;
}

__global__ void final_softmax(const float* __restrict__ S, float* __restrict__ out)
{
    int b = blockIdx.x, tid = threadIdx.x;
    __shared__ float red[256];
    const float4* row4 = (const float4*)(S + (size_t)b * SLD);
    const int n4 = SLD / 4;

    float mx = -1e30f;
    for (int i = tid; i < n4; i += 256) {
        float4 x = row4[i];
        mx = fmaxf(mx, fmaxf(fmaxf(x.x, x.y), fmaxf(x.z, x.w)));
    }
    red[tid] = mx;
    __syncthreads();
    for (int s = 128; s > 0; s >>= 1) { if (tid < s) red[tid] = fmaxf(red[tid], red[tid + s]); __syncthreads(); }
    mx = red[0];
    __syncthreads();

    float sm = 0.f;
    for (int i = tid; i < n4; i += 256) {
        float4 x = row4[i];
        sm += __expf(x.x - mx) + __expf(x.y - mx) + __expf(x.z - mx) + __expf(x.w - mx);
    }
    red[tid] = sm;
    __syncthreads();
    for (int s = 128; s > 0; s >>= 1) { if (tid < s) red[tid] += red[tid + s]; __syncthreads(); }
    float inv = __fdividef(1.f, red[0]);

    const float4* cp4 = (const float4*)(S + (size_t)b * SLD + VOC);
    float4* out4 = (float4*)(out + (size_t)b * PV);
    for (int i = tid; i < PV / 4; i += 256) {
        float4 c = cp4[i];
        float4 o;
        o.x = __expf(c.x - mx) * inv;
        o.y = __expf(c.y - mx) * inv;
        o.z = __expf(c.z - mx) * inv;
        o.w = __expf(c.w - mx) * inv;
        if (i < VOC / 4) {
            float4 g = row4[i];
            o.x += __expf(g.x - mx) * inv;
            o.y += __expf(g.y - mx) * inv;
            o.z += __expf(g.z - mx) * inv;
            o.w += __expf(g.w - mx) * inv;
        }
        out4[i] = o;
    }
}

// ---------------------------------------------------------------------------
static cudaStream_t g_s1, g_s2, g_s3;
static cudaEvent_t g_evRoot, g_evWP, g_evZ, g_evU, g_evGH, g_evG, g_evCS, g_evS;
static bool g_init = false;

extern "C" void kernel_launch(void* const* d_in, const int* in_sizes, int n_in,
                              void* d_out, int out_size)
{
    if (!g_init) {
        cudaStreamCreateWithFlags(&g_s1, cudaStreamNonBlocking);
        cudaStreamCreateWithFlags(&g_s2, cudaStreamNonBlocking);
        cudaStreamCreateWithFlags(&g_s3, cudaStreamNonBlocking);
        cudaEventCreateWithFlags(&g_evRoot, cudaEventDisableTiming);
        cudaEventCreateWithFlags(&g_evWP,   cudaEventDisableTiming);
        cudaEventCreateWithFlags(&g_evZ,    cudaEventDisableTiming);
        cudaEventCreateWithFlags(&g_evU,    cudaEventDisableTiming);
        cudaEventCreateWithFlags(&g_evGH,   cudaEventDisableTiming);
        cudaEventCreateWithFlags(&g_evG,    cudaEventDisableTiming);
        cudaEventCreateWithFlags(&g_evCS,   cudaEventDisableTiming);
        cudaEventCreateWithFlags(&g_evS,    cudaEventDisableTiming);
        cudaFuncSetAttribute(gemm_tf32<0>, cudaFuncAttributeMaxDynamicSharedMemorySize, GSMEM);
        cudaFuncSetAttribute(gemm_tf32<1>, cudaFuncAttributeMaxDynamicSharedMemorySize, GSMEM);
        cudaFuncSetAttribute(gemm_tf32<2>, cudaFuncAttributeMaxDynamicSharedMemorySize, GSMEM);
        g_init = true;
    }

    const float* z_enc  = (const float*)d_in[0];
    const float* u_enc  = (const float*)d_in[1];
    const int*   mt     = (const int*)d_in[2];
    const float* degree = (const float*)d_in[3];
    const float* hid    = (const float*)d_in[4];
    const float* sp     = (const float*)d_in[5];
    const float* emb    = (const float*)d_in[6];
    const float* azW    = (const float*)d_in[7];
    const float* azb    = (const float*)d_in[8];
    const float* azv    = (const float*)d_in[9];
    const float* auW    = (const float*)d_in[10];
    const float* aub    = (const float*)d_in[11];
    const float* auv    = (const float*)d_in[12];
    const float* Wih    = (const float*)d_in[13];
    const float* Whh    = (const float*)d_in[14];
    const float* bih    = (const float*)d_in[15];
    const float* bhh    = (const float*)d_in[16];
    const float* pW     = (const float*)d_in[17];
    const float* pb     = (const float*)d_in[18];
    const float* c2W    = (const float*)d_in[19];
    const float* c2b    = (const float*)d_in[20];
    float* out = (float*)d_out;

    float* base = nullptr;
    cudaGetSymbolAddress((void**)&base, g_scratch);
    float* ppz    = base + OFF_PPZ;
    float* ppu    = base + OFF_PPU;
    float* preZ   = base + OFF_PREZ;
    float* preU   = base + OFF_PREU;
    float* partZ  = base + OFF_PARTZ;
    float* partU  = base + OFF_PARTU;
    float* partGH = base + OFF_PARTGH;
    float* partGI = base + OFF_PARTGI;
    float* partPJ = base + OFF_PARTPJ;
    float* P      = base + OFF_P;
    float* G      = base + OFF_G;
    float* memb   = base + OFF_MEMB;
    float* degp   = base + OFF_DEGP;
    float* gi     = base + OFF_GI;
    float* gh     = base + OFF_GH;
    float* hnew   = base + OFF_HNEW;
    float* hnewR  = base + OFF_HNEWR;
    float* S      = base + OFF_S;
    float* ez     = base + OFF_EZ;
    float* mz     = base + OFF_MZ;
    float* Wihp   = base + OFF_WIHP;
    float* cs     = base + OFF_CS;

    // ---- fork ----
    cudaEventRecord(g_evRoot, 0);
    cudaStreamWaitEvent(g_s1, g_evRoot, 0);
    cudaStreamWaitEvent(g_s2, g_evRoot, 0);
    cudaStreamWaitEvent(g_s3, g_evRoot, 0);

    // ---- s2: cs = tanh(z_enc @ c2W^T + c2b) at t=0 ----
    gemm_tf32<2><<<dim3(4, 64, 1), 256, GSMEM, g_s2>>>(z_enc, HDIM, c2W, HDIM, 0,
        c2b, nullptr, nullptr, cs, HDIM, TZ*BATCH, HDIM, HDIM);
    cudaEventRecord(g_evCS, g_s2);

    // ---- s3: Wih pad, embed/deg, gi0 (slices 0-3), gi2 (slice 4), gh (8 slices) ----
    padWih<<<(NG * GINP + 255) / 256, 256, 0, g_s3>>>(Wih, Wihp);
    build_embdeg<<<BATCH, 128, 0, g_s3>>>(mt, emb, degree, memb, degp);
    gemm_tf32<0><<<dim3(12, 1, 4), 256, GSMEM, g_s3>>>(memb, HDIM, Wihp, GINP, 0,
        nullptr, nullptr, nullptr, partGI, NG, BATCH, NG, HDIM);
    gemm_tf32<0><<<dim3(12, 1, 1), 256, GSMEM, g_s3>>>(degp, 16, Wihp, GINP, 1536,
        nullptr, nullptr, nullptr, partGI + 4 * (size_t)BATCH * NG, NG, BATCH, NG, 16);
    cudaEventRecord(g_evWP, g_s3);
    gemm_tf32<0><<<dim3(12, 1, 8), 256, GSMEM, g_s3>>>(hid, HDIM, Whh, HDIM, 0,
        nullptr, nullptr, nullptr, partGH, NG, BATCH, NG, HDIM);
    reduceK<<<(BATCH * NG + 255) / 256, 256, 0, g_s3>>>(partGH, 8, BATCH, NG, bhh, gh, NG);
    cudaEventRecord(g_evGH, g_s3);

    // ---- default: Z chain ----
    gemm_tf32<0><<<dim3(4, 1, 8), 256, GSMEM>>>(hid, HDIM, azW, 2*HDIM, 0,
        nullptr, nullptr, nullptr, ppz, HDIM, BATCH, HDIM, HDIM);
    reduceK<<<(BATCH * HDIM + 255) / 256, 256>>>(ppz, 8, BATCH, HDIM, azb, preZ, HDIM);
    gemm_tf32<1><<<dim3(4, 64, 1), 256, GSMEM>>>(z_enc, HDIM, azW, 2*HDIM, HDIM,
        nullptr, preZ, azv, partZ, 0, TZ*BATCH, HDIM, HDIM);
    softmax_ctx<<<BATCH, 128>>>(partZ, z_enc, P, G + 512, TZ);
    cudaEventRecord(g_evZ, 0);

    // ---- s1: U chain ----
    gemm_tf32<0><<<dim3(4, 1, 8), 256, GSMEM, g_s1>>>(hid, HDIM, auW, 2*HDIM, 0,
        nullptr, nullptr, nullptr, ppu, HDIM, BATCH, HDIM, HDIM);
    reduceK<<<(BATCH * HDIM + 255) / 256, 256, 0, g_s1>>>(ppu, 8, BATCH, HDIM, aub, preU, HDIM);
    gemm_tf32<1><<<dim3(4, 128, 1), 256, GSMEM, g_s1>>>(u_enc, HDIM, auW, 2*HDIM, HDIM,
        nullptr, preU, auv, partU, 0, TU*BATCH, HDIM, HDIM);
    softmax_ctx<<<BATCH, 128, 0, g_s1>>>(partU, u_enc, P + 512, G, TU);
    cudaEventRecord(g_evU, g_s1);

    // ---- default: gi1 (slices 5-12, splitK=8) -> reduce(13) -> gru ----
    cudaStreamWaitEvent(0, g_evU, 0);
    cudaStreamWaitEvent(0, g_evWP, 0);
    gemm_tf32<0><<<dim3(12, 1, 8), 256, GSMEM>>>(G, 1024, Wihp, GINP, 512,
        nullptr, nullptr, nullptr, partGI + 5 * (size_t)BATCH * NG, NG, BATCH, NG, 1024);
    reduceK<<<(BATCH * NG + 255) / 256, 256>>>(partGI, 13, BATCH, NG, bih, gi, NG);
    cudaStreamWaitEvent(0, g_evGH, 0);
    gru_gate<<<(BATCH * HDIM) / 256, 256>>>(gi, gh, hid, hnew, hnewR, out, out_size);
    cudaEventRecord(g_evG, 0);

    // ---- s1: proj1 (ctx, slices 0-1) then proj2 (hnew, slices 2-3) ----
    cudaStreamWaitEvent(g_s1, g_evZ, 0);
    gemm_tf32<0><<<dim3(63, 1, 2), 256, GSMEM, g_s1>>>(P, 1024, pW, NG, 0,
        nullptr, nullptr, nullptr, partPJ, VOC, BATCH, VOC, 1024);
    cudaStreamWaitEvent(g_s1, g_evG, 0);
    gemm_tf32<0><<<dim3(63, 1, 2), 256, GSMEM, g_s1>>>(hnewR, HDIM, pW, NG, 1024,
        nullptr, nullptr, nullptr, partPJ + 2 * (size_t)BATCH * VOC, VOC, BATCH, VOC, HDIM);
    reduceK<<<(BATCH * VOC + 255) / 256, 256, 0, g_s1>>>(partPJ, 4, BATCH, VOC, pb, S, SLD);
    cudaEventRecord(g_evS, g_s1);

    // ---- default: fused zscore+exp -> zcopy ----
    cudaStreamWaitEvent(0, g_evCS, 0);
    zscore_exp<<<BATCH, 256>>>(cs, hnew, ez, mz);
    zcopy_kernel<<<dim3((PV / 4 + 255) / 256, BATCH), 256>>>(sp, ez, mz, S);

    // ---- join; final ----
    cudaStreamWaitEvent(0, g_evS, 0);
    final_softmax<<<BATCH, 256>>>(S, out);
}